// round 2
// baseline (speedup 1.0000x reference)
#include <cuda_runtime.h>

// ChamferLoss: pred[2048,8,3], gt[2048,8,3] -> scalar
// result = mean_i min_j dist(x_i, y_j) + mean_j min_i dist(x_i, y_j)
// Strategy: d2 = |x|^2 + min_y(|y|^2 - 2 x.y); sqrt is monotone -> sqrt once per point.
// Packed f32x2 FMA (Blackwell) processes 2 targets per chain; 2 queries per thread
// share each shared-memory target load.

typedef unsigned long long ull;

__device__ __forceinline__ ull pack2(float lo, float hi) {
    ull r; asm("mov.b64 %0,{%1,%2};" : "=l"(r) : "f"(lo), "f"(hi)); return r;
}
__device__ __forceinline__ ull fma2(ull a, ull b, ull c) {
    ull d; asm("fma.rn.f32x2 %0,%1,%2,%3;" : "=l"(d) : "l"(a), "l"(b), "l"(c)); return d;
}
__device__ __forceinline__ void unpack2(ull v, float& lo, float& hi) {
    asm("mov.b64 {%0,%1},%2;" : "=f"(lo), "=f"(hi) : "l"(v));
}

#define NPTS        16384      // points per cloud (2048 boxes * 8 corners)
#define NPAIR       8192       // target pairs per direction
#define TILE_PAIRS  1024       // pairs per smem tile (32 KB)
#define NTILES      (NPAIR / TILE_PAIRS)
#define MAIN_BLOCKS 128

// Packed target clouds. Per pair p: entry 2p = {pack(y0a,y0b), pack(y1a,y1b)},
// entry 2p+1 = {pack(y2a,y2b), pack(na,nb)}.  dir 0 targets = gt, dir 1 = pred.
__device__ ulonglong2 g_tgt[2][2 * NPAIR];
__device__ float g_partial[MAIN_BLOCKS];

__global__ void prep_kernel(const float* __restrict__ pred,
                            const float* __restrict__ gt) {
    int pid = blockIdx.x * blockDim.x + threadIdx.x;   // 0..16383
    int d   = pid >> 13;                               // direction
    int p   = pid & (NPAIR - 1);
    const float* src = (d == 0) ? gt : pred;
    const float* t0 = src + (2 * p) * 3;
    const float* t1 = src + (2 * p + 1) * 3;
    float a0 = t0[0], a1 = t0[1], a2 = t0[2];
    float b0 = t1[0], b1 = t1[1], b2 = t1[2];
    float na = a0 * a0 + a1 * a1 + a2 * a2;
    float nb = b0 * b0 + b1 * b1 + b2 * b2;
    ulonglong2 e0, e1;
    e0.x = pack2(a0, b0); e0.y = pack2(a1, b1);
    e1.x = pack2(a2, b2); e1.y = pack2(na, nb);
    g_tgt[d][2 * p]     = e0;
    g_tgt[d][2 * p + 1] = e1;
}

__global__ void __launch_bounds__(128, 1)
chamfer_main(const float* __restrict__ pred, const float* __restrict__ gt) {
    __shared__ ulonglong2 sT[2 * TILE_PAIRS];   // 32 KB

    int dir = blockIdx.x >> 6;       // blocks 0-63: dir 0 (queries=pred), 64-127: dir 1
    int sub = blockIdx.x & 63;
    int q0  = sub * 128 + threadIdx.x;   // 0..8191
    int q1  = q0 + 8192;

    const float* qsrc = (dir == 0) ? pred : gt;
    float x00 = qsrc[q0 * 3], x01 = qsrc[q0 * 3 + 1], x02 = qsrc[q0 * 3 + 2];
    float x10 = qsrc[q1 * 3], x11 = qsrc[q1 * 3 + 1], x12 = qsrc[q1 * 3 + 2];
    float n0 = x00 * x00 + x01 * x01 + x02 * x02;
    float n1 = x10 * x10 + x11 * x11 + x12 * x12;

    // broadcast -2*x coefficients, packed
    ull A00 = pack2(-2.0f * x00, -2.0f * x00);
    ull A01 = pack2(-2.0f * x01, -2.0f * x01);
    ull A02 = pack2(-2.0f * x02, -2.0f * x02);
    ull A10 = pack2(-2.0f * x10, -2.0f * x10);
    ull A11 = pack2(-2.0f * x11, -2.0f * x11);
    ull A12 = pack2(-2.0f * x12, -2.0f * x12);

    float m0[4], m1[4];
#pragma unroll
    for (int i = 0; i < 4; i++) { m0[i] = 3.0e38f; m1[i] = 3.0e38f; }

    const ulonglong2* gsrc = g_tgt[dir];

    for (int tile = 0; tile < NTILES; ++tile) {
        const ulonglong2* src = gsrc + tile * (2 * TILE_PAIRS);
#pragma unroll
        for (int i = 0; i < (2 * TILE_PAIRS) / 128; i++)
            sT[threadIdx.x + i * 128] = src[threadIdx.x + i * 128];
        __syncthreads();

#pragma unroll 8
        for (int p = 0; p < TILE_PAIRS; ++p) {
            ulonglong2 E0 = sT[2 * p];
            ulonglong2 E1 = sT[2 * p + 1];
            // t = |y|^2 - 2 x.y   for 2 targets at once
            ull t0 = fma2(A02, E1.x, E1.y);
            t0     = fma2(A01, E0.y, t0);
            t0     = fma2(A00, E0.x, t0);
            ull t1 = fma2(A12, E1.x, E1.y);
            t1     = fma2(A11, E0.y, t1);
            t1     = fma2(A10, E0.x, t1);
            float lo, hi;
            unpack2(t0, lo, hi);
            m0[p & 3] = fminf(m0[p & 3], fminf(lo, hi));
            unpack2(t1, lo, hi);
            m1[p & 3] = fminf(m1[p & 3], fminf(lo, hi));
        }
        __syncthreads();
    }

    float mm0 = fminf(fminf(m0[0], m0[1]), fminf(m0[2], m0[3]));
    float mm1 = fminf(fminf(m1[0], m1[1]), fminf(m1[2], m1[3]));
    float d0 = sqrtf(fmaxf(n0 + mm0, 0.0f));
    float d1 = sqrtf(fmaxf(n1 + mm1, 0.0f));
    float local = (d0 + d1) * (1.0f / 16384.0f);

    // deterministic block reduction
    __shared__ float sred[128];
    sred[threadIdx.x] = local;
    __syncthreads();
#pragma unroll
    for (int s = 64; s > 0; s >>= 1) {
        if (threadIdx.x < s) sred[threadIdx.x] += sred[threadIdx.x + s];
        __syncthreads();
    }
    if (threadIdx.x == 0) g_partial[blockIdx.x] = sred[0];
}

__global__ void finish_kernel(float* __restrict__ out) {
    __shared__ float s[MAIN_BLOCKS];
    s[threadIdx.x] = g_partial[threadIdx.x];
    __syncthreads();
#pragma unroll
    for (int st = 64; st > 0; st >>= 1) {
        if (threadIdx.x < st) s[threadIdx.x] += s[threadIdx.x + st];
        __syncthreads();
    }
    if (threadIdx.x == 0) out[0] = s[0];
}

extern "C" void kernel_launch(void* const* d_in, const int* in_sizes, int n_in,
                              void* d_out, int out_size) {
    const float* pred = (const float*)d_in[0];
    const float* gt   = (const float*)d_in[1];
    prep_kernel<<<64, 256>>>(pred, gt);
    chamfer_main<<<MAIN_BLOCKS, 128>>>(pred, gt);
    finish_kernel<<<1, MAIN_BLOCKS>>>((float*)d_out);
}

// round 5
// speedup vs baseline: 1.2905x; 1.2905x over previous
#include <cuda_runtime.h>

// ChamferLoss: pred[2048,8,3], gt[2048,8,3] -> scalar
// d2 = |x|^2 + min_y(|y|^2 - 2 x.y); sqrt is monotone -> one sqrt per query.
// Packed f32x2 FMA: 2 targets per chain. 4 queries per thread share each
// smem target load. 4-way target split gives 2 warps/SMSP for latency hiding.

typedef unsigned long long ull;

__device__ __forceinline__ ull pack2(float lo, float hi) {
    ull r; asm("mov.b64 %0,{%1,%2};" : "=l"(r) : "f"(lo), "f"(hi)); return r;
}
__device__ __forceinline__ ull fma2(ull a, ull b, ull c) {
    ull d; asm("fma.rn.f32x2 %0,%1,%2,%3;" : "=l"(d) : "l"(a), "l"(b), "l"(c)); return d;
}
__device__ __forceinline__ void unpack2(ull v, float& lo, float& hi) {
    asm("mov.b64 {%0,%1},%2;" : "=f"(lo), "=f"(hi) : "l"(v));
}
__device__ __forceinline__ void cpa16(unsigned dst, const void* src) {
    asm volatile("cp.async.cg.shared.global [%0], [%1], 16;" :: "r"(dst), "l"(src));
}
__device__ __forceinline__ void cpa_commit() { asm volatile("cp.async.commit_group;"); }
__device__ __forceinline__ void cpa_wait1() { asm volatile("cp.async.wait_group 1;"); }
__device__ __forceinline__ void cpa_wait0() { asm volatile("cp.async.wait_group 0;"); }

#define NPAIR        8192            // packed target pairs per direction
#define TILE_PAIRS   2048
#define TILE_ENTRIES (2 * TILE_PAIRS)   // ulonglong2 entries per tile (64 KB)
#define NTILES       (NPAIR / TILE_PAIRS)
#define MAIN_BLOCKS  128
#define MAIN_THREADS 256
#define SMEM_BYTES   (2 * TILE_ENTRIES * 16)   // 128 KB double buffer

// Packed targets: pair p -> entry 2p = {pack(y0a,y0b), pack(y1a,y1b)},
// entry 2p+1 = {pack(y2a,y2b), pack(|ya|^2,|yb|^2)}. dir0 targets=gt, dir1=pred.
__device__ ulonglong2 g_tgt[2][2 * NPAIR];
__device__ float g_partial[MAIN_BLOCKS];

__global__ void prep_kernel(const float* __restrict__ pred,
                            const float* __restrict__ gt) {
    int pid = blockIdx.x * blockDim.x + threadIdx.x;   // 0..16383
    int d   = pid >> 13;
    int p   = pid & (NPAIR - 1);
    const float* src = (d == 0) ? gt : pred;
    const float* t0 = src + (2 * p) * 3;
    const float* t1 = src + (2 * p + 1) * 3;
    float a0 = t0[0], a1 = t0[1], a2 = t0[2];
    float b0 = t1[0], b1 = t1[1], b2 = t1[2];
    float na = a0 * a0 + a1 * a1 + a2 * a2;
    float nb = b0 * b0 + b1 * b1 + b2 * b2;
    ulonglong2 e0, e1;
    e0.x = pack2(a0, b0); e0.y = pack2(a1, b1);
    e1.x = pack2(a2, b2); e1.y = pack2(na, nb);
    g_tgt[d][2 * p]     = e0;
    g_tgt[d][2 * p + 1] = e1;
}

__global__ void __launch_bounds__(MAIN_THREADS, 1)
chamfer_main(const float* __restrict__ pred, const float* __restrict__ gt) {
    extern __shared__ ulonglong2 sm[];      // [2][TILE_ENTRIES]
    __shared__ float red[64];

    int t   = threadIdx.x;
    int dir = blockIdx.x >> 6;              // 0: queries=pred, 1: queries=gt
    int sub = blockIdx.x & 63;
    int s   = t >> 6;                       // target slice 0..3 (warp-uniform)
    int qi  = t & 63;

    const float* qsrc = (dir == 0) ? pred : gt;
    int qbase = sub * 256 + qi * 4;

    ull  A[4][3];
    float n[4];
#pragma unroll
    for (int j = 0; j < 4; j++) {
        int q = qbase + j;
        float x0 = qsrc[3 * q], x1 = qsrc[3 * q + 1], x2 = qsrc[3 * q + 2];
        n[j] = x0 * x0 + x1 * x1 + x2 * x2;
        A[j][0] = pack2(-2.0f * x0, -2.0f * x0);
        A[j][1] = pack2(-2.0f * x1, -2.0f * x1);
        A[j][2] = pack2(-2.0f * x2, -2.0f * x2);
    }

    float m[4][2];
#pragma unroll
    for (int j = 0; j < 4; j++) { m[j][0] = 3.0e38f; m[j][1] = 3.0e38f; }

    const ulonglong2* g = g_tgt[dir];
    unsigned sbase = (unsigned)__cvta_generic_to_shared(sm);

    // prefetch tiles 0 and 1
#pragma unroll
    for (int i = 0; i < TILE_ENTRIES / MAIN_THREADS; i++) {
        int e = t + i * MAIN_THREADS;
        cpa16(sbase + (unsigned)(0 * TILE_ENTRIES + e) * 16, g + 0 * TILE_ENTRIES + e);
    }
    cpa_commit();
#pragma unroll
    for (int i = 0; i < TILE_ENTRIES / MAIN_THREADS; i++) {
        int e = t + i * MAIN_THREADS;
        cpa16(sbase + (unsigned)(1 * TILE_ENTRIES + e) * 16, g + 1 * TILE_ENTRIES + e);
    }
    cpa_commit();

    for (int T = 0; T < NTILES; T++) {
        if (T < NTILES - 1) cpa_wait1(); else cpa_wait0();
        __syncthreads();

        const ulonglong2* B = sm + (T & 1) * TILE_ENTRIES + s * (2 * (TILE_PAIRS / 4));
#pragma unroll 4
        for (int p = 0; p < TILE_PAIRS / 4; p++) {
            ulonglong2 E0 = B[2 * p];
            ulonglong2 E1 = B[2 * p + 1];
#pragma unroll
            for (int j = 0; j < 4; j++) {
                ull tt = fma2(A[j][2], E1.x, E1.y);
                tt     = fma2(A[j][1], E0.y, tt);
                tt     = fma2(A[j][0], E0.x, tt);
                float lo, hi;
                unpack2(tt, lo, hi);
                m[j][p & 1] = fminf(m[j][p & 1], fminf(lo, hi));
            }
        }

        if (T < NTILES - 2) {
            __syncthreads();   // everyone done reading buffer (T&1) before overwrite
#pragma unroll
            for (int i = 0; i < TILE_ENTRIES / MAIN_THREADS; i++) {
                int e = t + i * MAIN_THREADS;
                cpa16(sbase + (unsigned)((T & 1) * TILE_ENTRIES + e) * 16,
                      g + (T + 2) * TILE_ENTRIES + e);
            }
            cpa_commit();
        }
    }

    __syncthreads();
    float* pm = (float*)sm;                  // reuse tile smem: [4][64][4]
#pragma unroll
    for (int j = 0; j < 4; j++)
        pm[(s * 64 + qi) * 4 + j] = fminf(m[j][0], m[j][1]);
    __syncthreads();

    if (t < 64) {
        float sum = 0.0f;
#pragma unroll
        for (int j = 0; j < 4; j++) {
            float mm = pm[(0 * 64 + t) * 4 + j];
#pragma unroll
            for (int ss = 1; ss < 4; ss++)
                mm = fminf(mm, pm[(ss * 64 + t) * 4 + j]);
            sum += sqrtf(fmaxf(n[j] + mm, 0.0f));   // s==0 thread owns same queries
        }
        red[t] = sum * (1.0f / 16384.0f);
    }
    __syncthreads();
#pragma unroll
    for (int st = 32; st > 0; st >>= 1) {
        if (t < st) red[t] += red[t + st];
        __syncthreads();
    }
    if (t == 0) g_partial[blockIdx.x] = red[0];
}

__global__ void finish_kernel(float* __restrict__ out) {
    __shared__ float s[MAIN_BLOCKS];
    s[threadIdx.x] = g_partial[threadIdx.x];
    __syncthreads();
#pragma unroll
    for (int st = 64; st > 0; st >>= 1) {
        if (threadIdx.x < st) s[threadIdx.x] += s[threadIdx.x + st];
        __syncthreads();
    }
    if (threadIdx.x == 0) out[0] = s[0];
}

extern "C" void kernel_launch(void* const* d_in, const int* in_sizes, int n_in,
                              void* d_out, int out_size) {
    const float* pred = (const float*)d_in[0];
    const float* gt   = (const float*)d_in[1];
    cudaFuncSetAttribute(chamfer_main, cudaFuncAttributeMaxDynamicSharedMemorySize,
                         SMEM_BYTES);
    prep_kernel<<<64, 256>>>(pred, gt);
    chamfer_main<<<MAIN_BLOCKS, MAIN_THREADS, SMEM_BYTES>>>(pred, gt);
    finish_kernel<<<1, MAIN_BLOCKS>>>((float*)d_out);
}